// round 15
// baseline (speedup 1.0000x reference)
#include <cuda_runtime.h>
#include <cuda_fp16.h>
#include <math.h>
#include <stdint.h>

#define BB 2048
#define SS 200
#define DD 128
#define HH 64
#define MASK_SCALE 1e10f
#define NT 256
#define NW (NT / 32)
#define NSTRIP 13                    // ceil(200/16); strip 12 rows clamped

#define BSTRIDE 144                  // bytes per B row (72 fp16) = 9*16

// ---- main-kernel smem layout (no A tile!) ----
#define B_OFF      0                         // 128*144 = 18432
#define SM_ALPHA   18432                     // 256 f -> 19456
#define SM_CO      19456                     // 64 float2 -> 19968
#define SM_SCR     19968                     // 8*128 f -> 24064
#define SM_RED     24064                     // 8 f
#define SM_RED2    24096                     // 8 f
#define SMEM_BYTES 24128                     // 23.6 KB

typedef unsigned long long u64;

__device__ __half g_Bh[DD * 72];   // (W1+W2) fp16, [k][c] padded to 72
__device__ float g_Wb[DD * HH];    // W3 - W2
__device__ float g_c[BB * HH];     // tgt @ Wb + W_bias

__device__ __forceinline__ uint32_t smem_u32(const void* p) {
    return (uint32_t)__cvta_generic_to_shared(p);
}
__device__ __forceinline__ void cpa16(void* s, const void* g) {
    asm volatile("cp.async.cg.shared.global [%0], [%1], 16;" :: "r"(smem_u32(s)), "l"(g));
}
#define CP_COMMIT() asm volatile("cp.async.commit_group;")
#define CP_WAIT0()  asm volatile("cp.async.wait_group 0;")

__device__ __forceinline__ void ldsm4t(uint32_t* r, uint32_t addr) {
    asm volatile("ldmatrix.sync.aligned.m8n8.x4.trans.shared.b16 {%0,%1,%2,%3}, [%4];"
                 : "=r"(r[0]), "=r"(r[1]), "=r"(r[2]), "=r"(r[3]) : "r"(addr));
}
__device__ __forceinline__ void mma16816(float* c, const uint32_t* a,
                                         uint32_t b0, uint32_t b1) {
    asm volatile(
        "mma.sync.aligned.m16n8k16.row.col.f32.f16.f16.f32 "
        "{%0,%1,%2,%3}, {%4,%5,%6,%7}, {%8,%9}, {%0,%1,%2,%3};"
        : "+f"(c[0]), "+f"(c[1]), "+f"(c[2]), "+f"(c[3])
        : "r"(a[0]), "r"(a[1]), "r"(a[2]), "r"(a[3]), "r"(b0), "r"(b1));
}
__device__ __forceinline__ uint32_t h2(float2 v) {
    __half2 h = __floats2half2_rn(v.x, v.y);
    return *(uint32_t*)&h;
}

__global__ void fold_w_kernel(const float* __restrict__ W) {
    int idx = blockIdx.x * blockDim.x + threadIdx.x;
    if (idx < DD * HH) {
        int k = idx >> 6, c = idx & 63;
        float w1 = W[k * HH + c];
        float w2 = W[(DD + k) * HH + c];
        float w3 = W[(2 * DD + k) * HH + c];
        g_Wb[k * HH + c] = w3 - w2;
        g_Bh[k * 72 + c] = __float2half_rn(w1 + w2);
    }
}

__global__ void cvec_kernel(const float* __restrict__ target,
                            const float* __restrict__ W_bias) {
    __shared__ float tgt[DD];
    int b = blockIdx.x;
    for (int i = threadIdx.x; i < DD; i += blockDim.x)
        tgt[i] = target[(size_t)b * DD + i];
    __syncthreads();
    int h = threadIdx.x;
    if (h < HH) {
        float acc = 0.f;
#pragma unroll 8
        for (int d = 0; d < DD; d++)
            acc = fmaf(tgt[d], g_Wb[d * HH + h], acc);
        g_c[b * HH + h] = acc + W_bias[h];
    }
}

// ---- main kernel: A fed straight from global; no A smem tile ----
__global__ __launch_bounds__(NT, 4)
void ta_main_kernel(const float* __restrict__ his,
                    const float* __restrict__ mask,
                    const float* __restrict__ O,
                    const float* __restrict__ O_bias,
                    float* __restrict__ out) {
    extern __shared__ __align__(16) char sm[];
    float*  alpha = (float*)(sm + SM_ALPHA);
    float2* cO_s  = (float2*)(sm + SM_CO);
    float*  scr   = (float*)(sm + SM_SCR);
    float*  red   = (float*)(sm + SM_RED);
    float*  red2  = (float*)(sm + SM_RED2);

    const int b = blockIdx.x;
    const int tid = threadIdx.x;
    const int wid = tid >> 5;
    const int lane = tid & 31;
    const uint32_t smem_base = smem_u32(sm);

    // ---- Phase 0: B cp.async; alpha pre-bias; cO ----
    for (int i = tid; i < 18432 / 16; i += NT)
        cpa16(sm + B_OFF + i * 16, (const char*)g_Bh + i * 16);
    CP_COMMIT();

    const float ob = O_bias[0];
    if (tid < SS) alpha[tid] = ob - mask[(size_t)b * SS + tid] * MASK_SCALE;
    if (tid < HH) cO_s[tid] = make_float2(g_c[b * HH + tid], O[tid]);

    CP_WAIT0();
    __syncthreads();

    // ---- Phase 1: GEMM, A from global (sector-coalesced LDG.64) ----
    {
        const int g = lane >> 3;
        const int r = lane & 7;
        const int brow_l = r + (g & 1) * 8;
        const uint32_t bH = smem_base + B_OFF + brow_l * BSTRIDE + (g >> 1) * 16;
        const int qr = lane >> 2;            // 0..7
        const int qk = lane & 3;             // 0..3
        const float* Ab = his + (size_t)b * SS * DD;
        const int cbase = 2 * (lane & 3);

#pragma unroll 1
        for (int rnd = 0; rnd < 2; rnd++) {
            const int strip = wid + rnd * 8;
            if (strip >= NSTRIP) break;
            const int r0 = strip * 16 + qr;
            const int r1 = r0 + 8;
            const float* p0 = Ab + (size_t)((r0 < SS) ? r0 : SS - 1) * DD + 2 * qk;
            const float* p1 = Ab + (size_t)((r1 < SS) ? r1 : SS - 1) * DD + 2 * qk;

            float c[8][4];
#pragma unroll
            for (int nt = 0; nt < 8; nt++)
#pragma unroll
                for (int q = 0; q < 4; q++) c[nt][q] = 0.f;

            // prefetch kk=0
            float2 ra0 = *(const float2*)(p0);
            float2 ra1 = *(const float2*)(p1);
            float2 ra2 = *(const float2*)(p0 + 8);
            float2 ra3 = *(const float2*)(p1 + 8);

#pragma unroll
            for (int kk = 0; kk < 8; kk++) {
                uint32_t af[4];
                af[0] = h2(ra0); af[1] = h2(ra1); af[2] = h2(ra2); af[3] = h2(ra3);
                if (kk < 7) {
                    const int ko = (kk + 1) * 16;
                    ra0 = *(const float2*)(p0 + ko);
                    ra1 = *(const float2*)(p1 + ko);
                    ra2 = *(const float2*)(p0 + ko + 8);
                    ra3 = *(const float2*)(p1 + ko + 8);
                }
                const uint32_t koff = kk * 16 * BSTRIDE;
#pragma unroll
                for (int np2 = 0; np2 < 4; np2++) {
                    uint32_t bf[4];
                    ldsm4t(bf, bH + koff + np2 * 32);
                    mma16816(c[2 * np2],     af, bf[0], bf[1]);
                    mma16816(c[2 * np2 + 1], af, bf[2], bf[3]);
                }
            }

            float v0 = 0.f, v1 = 0.f;
#pragma unroll
            for (int nt = 0; nt < 8; nt++) {
                int col0 = nt * 8 + cbase;
                float2 co0 = cO_s[col0];
                float2 co1 = cO_s[col0 + 1];
                v0 = fmaf(fmaxf(c[nt][0] + co0.x, 0.f), co0.y, v0);
                v0 = fmaf(fmaxf(c[nt][1] + co1.x, 0.f), co1.y, v0);
                v1 = fmaf(fmaxf(c[nt][2] + co0.x, 0.f), co0.y, v1);
                v1 = fmaf(fmaxf(c[nt][3] + co1.x, 0.f), co1.y, v1);
            }
            v0 += __shfl_xor_sync(0xffffffffu, v0, 1);
            v0 += __shfl_xor_sync(0xffffffffu, v0, 2);
            v1 += __shfl_xor_sync(0xffffffffu, v1, 1);
            v1 += __shfl_xor_sync(0xffffffffu, v1, 2);
            if ((lane & 3) == 0) {
                int s0 = strip * 16 + qr;
                if (s0 < SS)     alpha[s0]     = v0 + alpha[s0];
                if (s0 + 8 < SS) alpha[s0 + 8] = v1 + alpha[s0 + 8];
            }
        }
    }
    __syncthreads();

    // ---- Phase 2: softmax over alpha[0..SS) ----
    {
        float vv = (tid < SS) ? alpha[tid] : -INFINITY;
        float m = vv;
#pragma unroll
        for (int off = 16; off > 0; off >>= 1)
            m = fmaxf(m, __shfl_xor_sync(0xffffffffu, m, off));
        if (lane == 0) red[wid] = m;
        __syncthreads();
        m = red[0];
#pragma unroll
        for (int w = 1; w < NW; w++) m = fmaxf(m, red[w]);

        float e = (tid < SS) ? __expf(vv - m) : 0.f;
        float ssum = e;
#pragma unroll
        for (int off = 16; off > 0; off >>= 1)
            ssum += __shfl_xor_sync(0xffffffffu, ssum, off);
        if (lane == 0) red2[wid] = ssum;
        __syncthreads();
        float tot = 0.f;
#pragma unroll
        for (int w = 0; w < NW; w++) tot += red2[w];

        if (tid < SS) alpha[tid] = e / tot;
    }
    __syncthreads();

    // ---- Phase 3: pooling from global (exact fp32; L1/L2-hot rows) ----
    {
        float a0 = 0.f, a1 = 0.f, a2 = 0.f, a3 = 0.f;
#pragma unroll 1
        for (int rnd = 0; rnd < 2; rnd++) {
            const int strip = wid + rnd * 8;
            if (strip >= NSTRIP) break;
            const int base = strip * 16;
            const int nrows = (base + 16 <= SS) ? 16 : (SS - base);
            const float* hp = his + ((size_t)b * SS + base) * DD + 4 * lane;
#pragma unroll 4
            for (int i = 0; i < nrows; i++) {
                float4 hv = *(const float4*)(hp + (size_t)i * DD);
                float a = alpha[base + i];
                a0 = fmaf(a, hv.x, a0);
                a1 = fmaf(a, hv.y, a1);
                a2 = fmaf(a, hv.z, a2);
                a3 = fmaf(a, hv.w, a3);
            }
        }
        *(float4*)(scr + wid * 128 + lane * 4) = make_float4(a0, a1, a2, a3);
        __syncthreads();
        if (tid < DD) {
            float r2 = 0.f;
#pragma unroll
            for (int g2 = 0; g2 < NW; g2++) r2 += scr[g2 * 128 + tid];
            out[(size_t)b * DD + tid] = r2;
        }
    }
}

extern "C" void kernel_launch(void* const* d_in, const int* in_sizes, int n_in,
                              void* d_out, int out_size) {
    const float* his    = (const float*)d_in[0];
    const float* target = (const float*)d_in[1];
    const float* mask   = (const float*)d_in[2];
    const float* W      = (const float*)d_in[3];
    const float* W_bias = (const float*)d_in[4];
    const float* O      = (const float*)d_in[5];
    const float* O_bias = (const float*)d_in[6];
    float* out = (float*)d_out;

    cudaFuncSetAttribute(ta_main_kernel,
                         cudaFuncAttributeMaxDynamicSharedMemorySize, SMEM_BYTES);

    fold_w_kernel<<<(DD * HH + 255) / 256, 256>>>(W);
    cvec_kernel<<<BB, 128>>>(target, W_bias);
    ta_main_kernel<<<BB, NT, SMEM_BYTES>>>(his, mask, O, O_bias, out);
}

// round 16
// speedup vs baseline: 1.1309x; 1.1309x over previous
#include <cuda_runtime.h>
#include <cuda_fp16.h>
#include <math.h>
#include <stdint.h>

#define BB 2048
#define SS 200
#define DD 128
#define HH 64
#define MASK_SCALE 1e10f
#define NT 256
#define NW (NT / 32)
#define NSTRIP 13                    // ceil(200/16); strip 12 rows 200..207 garbage-guarded

#define ASTRIDE 272                  // bytes per A row (136 fp16) = 17*16
#define BSTRIDE 144                  // bytes per B row (72 fp16)  = 9*16

// ---- main-kernel smem layout (R8 proven) ----
#define A_OFF      0                         // 200*272 = 54400
#define B_OFF      54400                     // 128*144 = 18432 (dead after GEMM)
#define SM_SCRATCH B_OFF                     // pool scratch aliases B: 8*128 f
#define SM_RED     (B_OFF + 4096)            // 8 f (aliases B)
#define SM_RED2    (B_OFF + 4128)            // 8 f (aliases B)
#define SM_ALPHA   72832                     // 256 f
#define SM_CO      73856                     // 64 float2 = 512
#define SMEM_BYTES 74368                     // 72.6 KB; x3 = 218 KB/SM

#define CV_BPB 8

typedef unsigned long long u64;

__device__ __half g_Bh[DD * 72];   // (W1+W2) fp16, [k][c] padded to 72
__device__ float g_Wb[DD * HH];    // W3 - W2
__device__ float g_c[BB * HH];     // tgt @ Wb + W_bias

__device__ __forceinline__ uint32_t smem_u32(const void* p) {
    return (uint32_t)__cvta_generic_to_shared(p);
}
__device__ __forceinline__ void cpa16(void* s, const void* g) {
    asm volatile("cp.async.cg.shared.global [%0], [%1], 16;" :: "r"(smem_u32(s)), "l"(g));
}
#define CP_COMMIT() asm volatile("cp.async.commit_group;")
#define CP_WAIT0()  asm volatile("cp.async.wait_group 0;")

__device__ __forceinline__ void ldsm4(uint32_t* r, uint32_t addr) {
    asm volatile("ldmatrix.sync.aligned.m8n8.x4.shared.b16 {%0,%1,%2,%3}, [%4];"
                 : "=r"(r[0]), "=r"(r[1]), "=r"(r[2]), "=r"(r[3]) : "r"(addr));
}
__device__ __forceinline__ void ldsm4t(uint32_t* r, uint32_t addr) {
    asm volatile("ldmatrix.sync.aligned.m8n8.x4.trans.shared.b16 {%0,%1,%2,%3}, [%4];"
                 : "=r"(r[0]), "=r"(r[1]), "=r"(r[2]), "=r"(r[3]) : "r"(addr));
}
__device__ __forceinline__ void mma16816(float* c, const uint32_t* a,
                                         uint32_t b0, uint32_t b1) {
    asm volatile(
        "mma.sync.aligned.m16n8k16.row.col.f32.f16.f16.f32 "
        "{%0,%1,%2,%3}, {%4,%5,%6,%7}, {%8,%9}, {%0,%1,%2,%3};"
        : "+f"(c[0]), "+f"(c[1]), "+f"(c[2]), "+f"(c[3])
        : "r"(a[0]), "r"(a[1]), "r"(a[2]), "r"(a[3]), "r"(b0), "r"(b1));
}

__global__ void fold_w_kernel(const float* __restrict__ W) {
    int idx = blockIdx.x * blockDim.x + threadIdx.x;
    if (idx < DD * HH) {
        int k = idx >> 6, c = idx & 63;
        float w1 = W[k * HH + c];
        float w2 = W[(DD + k) * HH + c];
        float w3 = W[(2 * DD + k) * HH + c];
        g_Wb[k * HH + c] = w3 - w2;
        g_Bh[k * 72 + c] = __float2half_rn(w1 + w2);
    }
}

// batched cvec: 8 batches per block, Wb staged once in smem
__global__ __launch_bounds__(256, 2)
void cvec_kernel(const float* __restrict__ target,
                 const float* __restrict__ W_bias) {
    __shared__ float Wb_s[DD * HH];          // 32 KB
    __shared__ float tgt_s[CV_BPB * DD];     // 4 KB
    const int tid = threadIdx.x;
    const int b0 = blockIdx.x * CV_BPB;

    for (int i = tid; i < DD * HH / 4; i += 256)
        ((float4*)Wb_s)[i] = ((const float4*)g_Wb)[i];
    for (int i = tid; i < CV_BPB * DD / 4; i += 256)
        ((float4*)tgt_s)[i] = ((const float4*)(target + (size_t)b0 * DD))[i];
    __syncthreads();

    const int h = tid & 63;
    const int r2 = tid >> 6;
    const float wb = W_bias[h];
#pragma unroll
    for (int pass = 0; pass < 2; pass++) {
        const int r = r2 + pass * 4;
        float acc = 0.f;
#pragma unroll 8
        for (int k = 0; k < DD; k++)
            acc = fmaf(tgt_s[r * DD + k], Wb_s[k * HH + h], acc);
        g_c[(size_t)(b0 + r) * HH + h] = acc + wb;
    }
}

// ---- main kernel: R8 structure, n-chunked GEMM for occ-3 ----
__global__ __launch_bounds__(NT, 3)
void ta_main_kernel(const float* __restrict__ his,
                    const float* __restrict__ mask,
                    const float* __restrict__ O,
                    const float* __restrict__ O_bias,
                    float* __restrict__ out) {
    extern __shared__ __align__(16) char sm[];
    float*  alpha = (float*)(sm + SM_ALPHA);
    float2* cO_s  = (float2*)(sm + SM_CO);
    float*  scr   = (float*)(sm + SM_SCRATCH);
    float*  red   = (float*)(sm + SM_RED);
    float*  red2  = (float*)(sm + SM_RED2);

    const int b = blockIdx.x;
    const int tid = threadIdx.x;
    const int wid = tid >> 5;
    const int lane = tid & 31;
    const uint32_t smem_base = smem_u32(sm);

    // ---- Phase 0a: B weights via cp.async; alpha pre-bias; cO ----
    for (int i = tid; i < 18432 / 16; i += NT)
        cpa16(sm + B_OFF + i * 16, (const char*)g_Bh + i * 16);
    CP_COMMIT();

    const float ob = O_bias[0];
    if (tid < SS) alpha[tid] = ob - mask[(size_t)b * SS + tid] * MASK_SCALE;
    if (tid < HH) cO_s[tid] = make_float2(g_c[b * HH + tid], O[tid]);

    CP_WAIT0();
    __syncthreads();

    // ---- Phase 0b: own-strip loading (warp-local), 8-deep LDG batches ----
    {
        const int k0 = 4 * lane;
#pragma unroll 1
        for (int rnd = 0; rnd < 2; rnd++) {
            const int strip = wid + rnd * 8;
            if (strip >= NSTRIP) break;
            const int base = strip * 16;
            const int nrows = (base + 16 <= SS) ? 16 : (SS - base);
            const float* hb = his + ((size_t)b * SS + base) * DD + k0;
#pragma unroll 1
            for (int g0 = 0; g0 < nrows; g0 += 8) {
                float4 v[8];
#pragma unroll
                for (int j = 0; j < 8; j++)
                    if (g0 + j < nrows) v[j] = *(const float4*)(hb + (size_t)(g0 + j) * DD);
#pragma unroll
                for (int j = 0; j < 8; j++)
                    if (g0 + j < nrows) {
                        int s = base + g0 + j;
                        __half2 p01 = __floats2half2_rn(v[j].x, v[j].y);
                        __half2 p23 = __floats2half2_rn(v[j].z, v[j].w);
                        u64 hp = ((u64)*(uint32_t*)&p23 << 32) | *(uint32_t*)&p01;
                        *(u64*)(sm + A_OFF + s * ASTRIDE + k0 * 2) = hp;
                    }
            }
        }
    }
    __syncwarp();

    // ---- Phase 1: GEMM, dual-strip, n-chunked (2 x 32 cols) ----
    {
        const int g = lane >> 3;
        const int r = lane & 7;
        const int arow_l = r + (g & 1) * 8;
        const int acol_l = (g >> 1) * 16;
        const int brow_l = r + (g & 1) * 8;
        const uint32_t aB = smem_base + A_OFF;
        const uint32_t bH = smem_base + B_OFF + brow_l * BSTRIDE + (g >> 1) * 16;

        const int strip0 = wid;
        const int strip1 = wid + 8;
        const bool two = (strip1 < NSTRIP);
        const uint32_t Ab0 = aB + (strip0 * 16 + arow_l) * ASTRIDE + acol_l;
        const uint32_t Ab1 = aB + (strip1 * 16 + arow_l) * ASTRIDE + acol_l;
        const int cbase = 2 * (lane & 3);

        float v00 = 0.f, v01 = 0.f, v10 = 0.f, v11 = 0.f;

#pragma unroll
        for (int chunk = 0; chunk < 2; chunk++) {
            float c0[4][4], c1[4][4];
#pragma unroll
            for (int nt = 0; nt < 4; nt++)
#pragma unroll
                for (int q = 0; q < 4; q++) { c0[nt][q] = 0.f; c1[nt][q] = 0.f; }

#pragma unroll
            for (int kk = 0; kk < 8; kk++) {
                uint32_t a0[4], a1[4];
                ldsm4(a0, Ab0 + kk * 32);
                if (two) ldsm4(a1, Ab1 + kk * 32);
                const uint32_t koff = kk * 16 * BSTRIDE + chunk * 64;
#pragma unroll
                for (int np2 = 0; np2 < 2; np2++) {
                    uint32_t bf[4];
                    ldsm4t(bf, bH + koff + np2 * 32);
                    mma16816(c0[2 * np2],     a0, bf[0], bf[1]);
                    mma16816(c0[2 * np2 + 1], a0, bf[2], bf[3]);
                    if (two) {
                        mma16816(c1[2 * np2],     a1, bf[0], bf[1]);
                        mma16816(c1[2 * np2 + 1], a1, bf[2], bf[3]);
                    }
                }
            }

            // fold chunk into logit partials
#pragma unroll
            for (int nt = 0; nt < 4; nt++) {
                int col0 = (chunk * 4 + nt) * 8 + cbase;
                float2 co0 = cO_s[col0];
                float2 co1 = cO_s[col0 + 1];
                v00 = fmaf(fmaxf(c0[nt][0] + co0.x, 0.f), co0.y, v00);
                v00 = fmaf(fmaxf(c0[nt][1] + co1.x, 0.f), co1.y, v00);
                v01 = fmaf(fmaxf(c0[nt][2] + co0.x, 0.f), co0.y, v01);
                v01 = fmaf(fmaxf(c0[nt][3] + co1.x, 0.f), co1.y, v01);
                v10 = fmaf(fmaxf(c1[nt][0] + co0.x, 0.f), co0.y, v10);
                v10 = fmaf(fmaxf(c1[nt][1] + co1.x, 0.f), co1.y, v10);
                v11 = fmaf(fmaxf(c1[nt][2] + co0.x, 0.f), co0.y, v11);
                v11 = fmaf(fmaxf(c1[nt][3] + co1.x, 0.f), co1.y, v11);
            }
        }

        v00 += __shfl_xor_sync(0xffffffffu, v00, 1);
        v00 += __shfl_xor_sync(0xffffffffu, v00, 2);
        v01 += __shfl_xor_sync(0xffffffffu, v01, 1);
        v01 += __shfl_xor_sync(0xffffffffu, v01, 2);
        v10 += __shfl_xor_sync(0xffffffffu, v10, 1);
        v10 += __shfl_xor_sync(0xffffffffu, v10, 2);
        v11 += __shfl_xor_sync(0xffffffffu, v11, 1);
        v11 += __shfl_xor_sync(0xffffffffu, v11, 2);

        if ((lane & 3) == 0) {
            const int qr = lane >> 2;
            int s0 = strip0 * 16 + qr;
            alpha[s0]     = v00 + alpha[s0];
            alpha[s0 + 8] = v01 + alpha[s0 + 8];
            if (two) {
                int s1 = strip1 * 16 + qr;
                if (s1 < SS)     alpha[s1]     = v10 + alpha[s1];
                if (s1 + 8 < SS) alpha[s1 + 8] = v11 + alpha[s1 + 8];
            }
        }
    }
    __syncthreads();

    // ---- Phase 2: softmax over alpha[0..SS) ----
    {
        float vv = (tid < SS) ? alpha[tid] : -INFINITY;
        float m = vv;
#pragma unroll
        for (int off = 16; off > 0; off >>= 1)
            m = fmaxf(m, __shfl_xor_sync(0xffffffffu, m, off));
        if (lane == 0) red[wid] = m;
        __syncthreads();
        m = red[0];
#pragma unroll
        for (int w = 1; w < NW; w++) m = fmaxf(m, red[w]);

        float e = (tid < SS) ? __expf(vv - m) : 0.f;
        float ssum = e;
#pragma unroll
        for (int off = 16; off > 0; off >>= 1)
            ssum += __shfl_xor_sync(0xffffffffu, ssum, off);
        if (lane == 0) red2[wid] = ssum;
        __syncthreads();
        float tot = 0.f;
#pragma unroll
        for (int w = 0; w < NW; w++) tot += red2[w];

        if (tid < SS) alpha[tid] = e / tot;
    }
    __syncthreads();

    // ---- Phase 3: pooling out[b,d] = sum_s attn[s]*A[s,d]  (LDS.64) ----
    {
        const int p = tid & 31;
        const int q = wid;
        float a0 = 0.f, a1 = 0.f, a2 = 0.f, a3 = 0.f;
        const int sbeg = q * 25;
#pragma unroll 5
        for (int i = 0; i < 25; i++) {
            int s = sbeg + i;
            uint2 hv = *(uint2*)(sm + A_OFF + s * ASTRIDE + p * 8);
            float2 f01 = __half22float2(*(__half2*)&hv.x);
            float2 f23 = __half22float2(*(__half2*)&hv.y);
            float a = alpha[s];
            a0 = fmaf(a, f01.x, a0);
            a1 = fmaf(a, f01.y, a1);
            a2 = fmaf(a, f23.x, a2);
            a3 = fmaf(a, f23.y, a3);
        }
        *(float4*)(scr + q * 128 + p * 4) = make_float4(a0, a1, a2, a3);
        __syncthreads();
        if (tid < DD) {
            float r2 = 0.f;
#pragma unroll
            for (int g2 = 0; g2 < NW; g2++) r2 += scr[g2 * 128 + tid];
            out[(size_t)b * DD + tid] = r2;
        }
    }
}

extern "C" void kernel_launch(void* const* d_in, const int* in_sizes, int n_in,
                              void* d_out, int out_size) {
    const float* his    = (const float*)d_in[0];
    const float* target = (const float*)d_in[1];
    const float* mask   = (const float*)d_in[2];
    const float* W      = (const float*)d_in[3];
    const float* W_bias = (const float*)d_in[4];
    const float* O      = (const float*)d_in[5];
    const float* O_bias = (const float*)d_in[6];
    float* out = (float*)d_out;

    cudaFuncSetAttribute(ta_main_kernel,
                         cudaFuncAttributeMaxDynamicSharedMemorySize, SMEM_BYTES);

    fold_w_kernel<<<(DD * HH + 255) / 256, 256>>>(W);
    cvec_kernel<<<BB / CV_BPB, 256>>>(target, W_bias);
    ta_main_kernel<<<BB, NT, SMEM_BYTES>>>(his, mask, O, O_bias, out);
}